// round 6
// baseline (speedup 1.0000x reference)
#include <cuda_runtime.h>

// out[bh][q*96+v] = K[bh,3,q] * u[v];  u = scale * (q3 @ V) @ W3
// 192 blocks, 576 threads = 24 col4-groups x 24 k-groups.
// No q/k smem staging: per-thread broadcast loads, phase-1 starts sync-free.

#define SD    96
#define C4    24      // float4 columns per row
#define KG    24      // k groups
#define KSPAN 4       // 96 / KG
#define NT    (C4 * KG)   // 576

__global__ __launch_bounds__(NT, 2) void mma73_kernel(
    const float* __restrict__ Q,
    const float* __restrict__ K,
    const float* __restrict__ V,
    const float* __restrict__ DW,
    const int*   __restrict__ uidx_p,
    float* __restrict__ out)
{
    const int tid = threadIdx.x;
    const int c4  = tid % C4;     // 0..23
    const int grp = tid / C4;     // 0..23
    const int bh  = blockIdx.x;   // 0..191

    __shared__ float t_s[SD];
    __shared__ __align__(16) float u_s[SD];
    __shared__ __align__(16) float part[KG][SD];

    const int uidx = *uidx_p;

    const float4* __restrict__ Vb4 = (const float4*)(V + (size_t)bh * SD * SD);
    const float4* __restrict__ W4  = (const float4*)(DW + (size_t)uidx * SD * SD);
    const size_t qk_base = ((size_t)bh * SD + 3) * SD;

    // ---- front-batched independent loads (MLP 16) ----
    float4 v_r[KSPAN], w_r[KSPAN];
    float  q_r[KSPAN], k_r[KSPAN];
    #pragma unroll
    for (int j = 0; j < KSPAN; ++j)
        v_r[j] = Vb4[(grp * KSPAN + j) * C4 + c4];
    #pragma unroll
    for (int j = 0; j < KSPAN; ++j)
        w_r[j] = W4[(grp * KSPAN + j) * C4 + c4];
    #pragma unroll
    for (int j = 0; j < KSPAN; ++j)
        q_r[j] = __ldg(Q + qk_base + grp * KSPAN + j);   // 24-way L1 broadcast
    #pragma unroll
    for (int j = 0; j < KSPAN; ++j)
        k_r[j] = __ldg(K + qk_base + j * KG + grp);      // store rows for phase 3

    // ---- phase 1 partial: no barrier needed before this ----
    {
        float4 a = make_float4(0.f, 0.f, 0.f, 0.f);
        #pragma unroll
        for (int j = 0; j < KSPAN; ++j) {
            a.x += q_r[j] * v_r[j].x;  a.y += q_r[j] * v_r[j].y;
            a.z += q_r[j] * v_r[j].z;  a.w += q_r[j] * v_r[j].w;
        }
        ((float4*)part[grp])[c4] = a;
    }
    __syncthreads();

    if (tid < SD) {
        float s = 0.f;
        #pragma unroll
        for (int g = 0; g < KG; ++g) s += part[g][tid];
        t_s[tid] = s;
    }
    __syncthreads();

    // ---- phase 2: u = scale * (t @ W3) ----
    {
        float4 a = make_float4(0.f, 0.f, 0.f, 0.f);
        #pragma unroll
        for (int j = 0; j < KSPAN; ++j) {
            const float ti = t_s[grp * KSPAN + j];
            a.x += ti * w_r[j].x;  a.y += ti * w_r[j].y;
            a.z += ti * w_r[j].z;  a.w += ti * w_r[j].w;
        }
        ((float4*)part[grp])[c4] = a;
    }
    __syncthreads();

    if (tid < SD) {
        float s = 0.f;
        #pragma unroll
        for (int g = 0; g < KG; ++g) s += part[g][tid];
        u_s[tid] = s * 0.10206207261596575f;   // 1/sqrt(96)
    }
    __syncthreads();

    // ---- phase 3: outer product; row q = r*24 + grp, col group c4 ----
    float4* __restrict__ O4 = (float4*)(out + (size_t)bh * SD * SD);
    const float4 u4 = ((const float4*)u_s)[c4];
    #pragma unroll
    for (int r = 0; r < KSPAN; ++r) {
        const float kq = k_r[r];
        float4 o;
        o.x = kq * u4.x;  o.y = kq * u4.y;
        o.z = kq * u4.z;  o.w = kq * u4.w;
        O4[(r * KG + grp) * C4 + c4] = o;
    }
}

extern "C" void kernel_launch(void* const* d_in, const int* in_sizes, int n_in,
                              void* d_out, int out_size)
{
    const float* Q  = (const float*)d_in[0];
    const float* K  = (const float*)d_in[1];
    const float* V  = (const float*)d_in[2];
    const float* DW = (const float*)d_in[3];
    const int* uidx = (const int*)d_in[4];
    float* out      = (float*)d_out;

    mma73_kernel<<<192, NT>>>(Q, K, V, DW, uidx, out);
}